// round 6
// baseline (speedup 1.0000x reference)
#include <cuda_runtime.h>
#include <cuda_fp16.h>
#include <math.h>
#include <cstdint>

#define NT 256
#define TILE_W 64
#define TILE_H 8
#define IMW 512
#define IMH 512
#define NCH 12
#define NBINS 256

struct Params { const float* p[27]; };

__device__ double g_sumsq[2];                    // [0]=x, [1]=delta
__device__ unsigned int g_hist[2][NCH][NBINS];   // [0]=x, [1]=delta

// zeroing split into 5 slices so ncu's "-s 5 -c 1" lands on predict_kernel
#define ZTOTAL (2 * NCH * NBINS)
__global__ void zero_slice_kernel(int slice) {
    const int per = (ZTOTAL + 4) / 5;
    int i = slice * per + blockIdx.x * blockDim.x + threadIdx.x;
    if (i < (slice + 1) * per && i < ZTOTAL) ((unsigned int*)g_hist)[i] = 0u;
    if (slice == 0 && blockIdx.x == 0 && threadIdx.x < 2) g_sumsq[threadIdx.x] = 0.0;
}

__device__ __forceinline__ uint32_t h2u(__half2 h) { return *reinterpret_cast<uint32_t*>(&h); }
__device__ __forceinline__ __half2 u2h(uint32_t u) { return *reinterpret_cast<__half2*>(&u); }

// pack (m0.lo+m0.hi, m1.lo+m1.hi) as one half2 — 2 PRMT + 1 HADD2
__device__ __forceinline__ __half2 hpair_sum(__half2 m0, __half2 m1) {
    __half2 lo = u2h(__byte_perm(h2u(m0), h2u(m1), 0x5410));
    __half2 hi = u2h(__byte_perm(h2u(m0), h2u(m1), 0x7632));
    return __hadd2(lo, hi);
}

__global__ __launch_bounds__(NT, 2) void predict_kernel(const float* __restrict__ x, Params prm) {
    // fp16x2 weights, K-pair packed, rows 16B-multiple strides for LDS.128
    __shared__ __align__(16) __half2 s_w0[3][32][12];      // layer0: 24 taps
    __shared__ __align__(16) __half2 s_w12[3][2][32][16];  // layers 1,2: 32 k
    __shared__ __align__(16) __half2 s_wh[3][16];          // head
    __shared__ __half2 s_bias[3][3][16];                   // channel-pair packed biases
    __shared__ float s_b3[3];
    __shared__ float s_tile[TILE_H + 3][TILE_W + 8];       // 11 x 70 used
    __shared__ unsigned int s_hist[2][NBINS];
    __shared__ double s_red[2][NT / 32];

    const int tx = threadIdx.x, ty = threadIdx.y;
    const int tid = ty * 32 + tx;
    const int ch  = blockIdx.z;
    const int gx0 = blockIdx.x * TILE_W;
    const int gy0 = blockIdx.y * TILE_H;

    for (int i = tid; i < 2 * NBINS; i += NT) ((unsigned int*)s_hist)[i] = 0u;

    // ---- stage weights fp32 -> fp16x2 ----
    for (int i = tid; i < 3 * 32 * 12; i += NT) {
        int p = i / 384, r = i % 384, oc = r / 12, q = r % 12;
        const float* wT = prm.p[p * 9 + 0];
        const float* wL = prm.p[p * 9 + 2];
        int k0 = 2 * q, k1 = 2 * q + 1;
        float f0 = (k0 < 21) ? wT[oc * 21 + k0] : wL[oc * 3 + (k0 - 21)];
        float f1 = (k1 < 21) ? wT[oc * 21 + k1] : wL[oc * 3 + (k1 - 21)];
        s_w0[p][oc][q] = __floats2half2_rn(f0, f1);
    }
    for (int i = tid; i < 3 * 2 * 32 * 16; i += NT) {
        int p = i / 1024, r = i % 1024, l = r / 512, r2 = r % 512, oc = r2 / 16, q = r2 % 16;
        const float* wm = prm.p[p * 9 + (l ? 5 : 3)];
        s_w12[p][l][oc][q] = __floats2half2_rn(wm[oc * 32 + 2 * q], wm[oc * 32 + 2 * q + 1]);
    }
    for (int i = tid; i < 3 * 16; i += NT) {
        int p = i / 16, q = i % 16;
        const float* w3 = prm.p[p * 9 + 7];
        s_wh[p][q] = __floats2half2_rn(w3[2 * q], w3[2 * q + 1]);
    }
    for (int i = tid; i < 3 * 3 * 16; i += NT) {
        int p = i / 48, r = i % 48, l = r / 16, q = r % 16;
        const float* b = prm.p[p * 9 + (l == 0 ? 1 : (l == 1 ? 4 : 6))];
        s_bias[p][l][q] = __floats2half2_rn(b[2 * q], b[2 * q + 1]);
    }
    if (tid < 3) s_b3[tid] = prm.p[tid * 9 + 8][0];

    // ---- stage input tile with halo ----
    const float* xch = x + (size_t)ch * IMH * IMW;
    for (int i = tid; i < (TILE_H + 3) * (TILE_W + 6); i += NT) {
        int r = i / (TILE_W + 6), c = i % (TILE_W + 6);
        int gr = gy0 - 3 + r, gc = gx0 - 3 + c;
        float v = 0.f;
        if (gr >= 0 && gc >= 0 && gc < IMW) v = xch[gr * IMW + gc];
        s_tile[r][c] = v;
    }
    __syncthreads();

    const __half2 C001 = __float2half2_rn(0.01f);
    double acc_x = 0.0, acc_d = 0.0;

    // ---- process 2 pixels sequentially (cols tx and tx+32) — low live-register set ----
#pragma unroll 1
    for (int px = 0; px < 2; ++px) {
        const int base = tx + px * 32;

        // gather taps, fp16x2 k-pairs
        __half2 t2[12];
        {
            float tp[24];
#pragma unroll
            for (int di = 0; di < 3; ++di)
#pragma unroll
                for (int dj = 0; dj < 7; ++dj) tp[di * 7 + dj] = s_tile[ty + di][base + dj];
#pragma unroll
            for (int dj = 0; dj < 3; ++dj) tp[21 + dj] = s_tile[ty + 3][base + dj];
#pragma unroll
            for (int q = 0; q < 12; ++q) t2[q] = __floats2half2_rn(tp[2 * q], tp[2 * q + 1]);
        }

        float preds[3];
#pragma unroll 1
        for (int p = 0; p < 3; ++p) {
            __half2 a1[16], a2[16];

            // ---- layer 0: 24 taps -> 32 ch ----
#pragma unroll
            for (int ocp = 0; ocp < 16; ++ocp) {
                const __half2* w0 = s_w0[p][2 * ocp];
                const __half2* w1 = s_w0[p][2 * ocp + 1];
                __half2 aA = __hmul2(w0[0], t2[0]);
                __half2 aB = __hmul2(w0[6], t2[6]);
                __half2 bA = __hmul2(w1[0], t2[0]);
                __half2 bB = __hmul2(w1[6], t2[6]);
#pragma unroll
                for (int q = 1; q < 6; ++q) {
                    aA = __hfma2(w0[q],     t2[q],     aA);
                    aB = __hfma2(w0[q + 6], t2[q + 6], aB);
                    bA = __hfma2(w1[q],     t2[q],     bA);
                    bB = __hfma2(w1[q + 6], t2[q + 6], bB);
                }
                __half2 s = __hadd2(hpair_sum(__hadd2(aA, aB), __hadd2(bA, bB)), s_bias[p][0][ocp]);
                a1[ocp] = __hmax2(s, __hmul2(s, C001));
            }

            // ---- layer 1: 32 -> 32 ----
#pragma unroll
            for (int ocp = 0; ocp < 16; ++ocp) {
                const __half2* w0 = s_w12[p][0][2 * ocp];
                const __half2* w1 = s_w12[p][0][2 * ocp + 1];
                __half2 aA = __hmul2(w0[0], a1[0]);
                __half2 aB = __hmul2(w0[8], a1[8]);
                __half2 bA = __hmul2(w1[0], a1[0]);
                __half2 bB = __hmul2(w1[8], a1[8]);
#pragma unroll
                for (int q = 1; q < 8; ++q) {
                    aA = __hfma2(w0[q],     a1[q],     aA);
                    aB = __hfma2(w0[q + 8], a1[q + 8], aB);
                    bA = __hfma2(w1[q],     a1[q],     bA);
                    bB = __hfma2(w1[q + 8], a1[q + 8], bB);
                }
                __half2 s = __hadd2(hpair_sum(__hadd2(aA, aB), __hadd2(bA, bB)), s_bias[p][1][ocp]);
                a2[ocp] = __hmax2(s, __hmul2(s, C001));
            }

            // ---- layer 2: 32 -> 32 ----
#pragma unroll
            for (int ocp = 0; ocp < 16; ++ocp) {
                const __half2* w0 = s_w12[p][1][2 * ocp];
                const __half2* w1 = s_w12[p][1][2 * ocp + 1];
                __half2 aA = __hmul2(w0[0], a2[0]);
                __half2 aB = __hmul2(w0[8], a2[8]);
                __half2 bA = __hmul2(w1[0], a2[0]);
                __half2 bB = __hmul2(w1[8], a2[8]);
#pragma unroll
                for (int q = 1; q < 8; ++q) {
                    aA = __hfma2(w0[q],     a2[q],     aA);
                    aB = __hfma2(w0[q + 8], a2[q + 8], aB);
                    bA = __hfma2(w1[q],     a2[q],     bA);
                    bB = __hfma2(w1[q + 8], a2[q + 8], bB);
                }
                __half2 s = __hadd2(hpair_sum(__hadd2(aA, aB), __hadd2(bA, bB)), s_bias[p][2][ocp]);
                a1[ocp] = __hmax2(s, __hmul2(s, C001));   // reuse a1 as h3
            }

            // ---- head: 32 -> 1 (fp16 dot, fp32 bias/clip) ----
            const __half2* wh = s_wh[p];
            __half2 aA = __hmul2(wh[0], a1[0]);
            __half2 aB = __hmul2(wh[8], a1[8]);
#pragma unroll
            for (int q = 1; q < 8; ++q) {
                aA = __hfma2(wh[q],     a1[q],     aA);
                aB = __hfma2(wh[q + 8], a1[q + 8], aB);
            }
            __half2 m = __hadd2(aA, aB);
            float a = __low2float(m) + __high2float(m) + s_b3[p];
            preds[p] = fminf(fmaxf(a, -1.f), 1.f);
        }

        // ---- stats ----
        const float x0 = s_tile[ty + 3][base + 3];
        const float pa = preds[0], pb = preds[1], pc = preds[2];
        const float med = fmaxf(fminf(pa, fmaxf(pb, pc)), fminf(pb, pc));
        const float delta = fmodf(x0 - med + 1.0f, 2.0f) - 1.0f;

        if (x0 >= -1.f && x0 <= 1.f) {
            int idx = (int)floorf((x0 + 1.f) * 128.f);
            idx = min(max(idx, 0), NBINS - 1);
            atomicAdd(&s_hist[0][idx], 1u);
        }
        if (delta >= -1.f && delta <= 1.f) {
            int idx = (int)floorf((delta + 1.f) * 128.f);
            idx = min(max(idx, 0), NBINS - 1);
            atomicAdd(&s_hist[1][idx], 1u);
        }
        acc_x += (double)x0 * (double)x0;
        acc_d += (double)delta * (double)delta;
    }

    // ---- reductions ----
#pragma unroll
    for (int o = 16; o > 0; o >>= 1) {
        acc_x += __shfl_down_sync(0xffffffffu, acc_x, o);
        acc_d += __shfl_down_sync(0xffffffffu, acc_d, o);
    }
    const int warp = tid >> 5, lane = tid & 31;
    if (lane == 0) { s_red[0][warp] = acc_x; s_red[1][warp] = acc_d; }
    __syncthreads();
    if (tid == 0) {
        double sx = 0.0, sd = 0.0;
#pragma unroll
        for (int i = 0; i < NT / 32; ++i) { sx += s_red[0][i]; sd += s_red[1][i]; }
        atomicAdd(&g_sumsq[0], sx);
        atomicAdd(&g_sumsq[1], sd);
    }
    if (tid < NBINS) {
        unsigned c0 = s_hist[0][tid], c1 = s_hist[1][tid];
        if (c0) atomicAdd(&g_hist[0][ch][tid], c0);
        if (c1) atomicAdd(&g_hist[1][ch][tid], c1);
    }
}

__global__ void finalize_kernel(float* out) {
    __shared__ double s_ent[2][8];
    const int tid = threadIdx.x;
    double e0 = 0.0, e1 = 0.0;
    const double res = (double)(IMH * IMW);
    for (int i = tid; i < NCH * NBINS; i += 256) {
        unsigned c0 = ((const unsigned*)g_hist[0])[i];
        unsigned c1 = ((const unsigned*)g_hist[1])[i];
        if (c0) { double pp = (double)c0 / res; e0 -= pp * log2(pp); }
        if (c1) { double pp = (double)c1 / res; e1 -= pp * log2(pp); }
    }
#pragma unroll
    for (int o = 16; o > 0; o >>= 1) {
        e0 += __shfl_down_sync(0xffffffffu, e0, o);
        e1 += __shfl_down_sync(0xffffffffu, e1, o);
    }
    if ((tid & 31) == 0) { s_ent[0][tid >> 5] = e0; s_ent[1][tid >> 5] = e1; }
    __syncthreads();
    if (tid == 0) {
        double E0 = 0.0, E1 = 0.0;
#pragma unroll
        for (int i = 0; i < 8; ++i) { E0 += s_ent[0][i]; E1 += s_ent[1][i]; }
        const double N = (double)NCH * IMH * IMW;
        out[0] = (float)(255.0 * sqrt(g_sumsq[1] / N));   // loss1
        out[1] = (float)(255.0 * sqrt(g_sumsq[0] / N));   // loss0
        out[2] = (float)(E0 / (8.0 * NCH));               // invCR0
        out[3] = (float)(E1 / (8.0 * NCH));               // invCR1
    }
}

extern "C" void kernel_launch(void* const* d_in, const int* in_sizes, int n_in,
                              void* d_out, int out_size) {
    const float* x = (const float*)d_in[0];
    Params prm;
    for (int i = 0; i < 27; ++i) prm.p[i] = (const float*)d_in[1 + i];

    // 5 zero launches (indices 0-4) so ncu "-s 5 -c 1" captures predict_kernel (index 5)
    const int per = (ZTOTAL + 4) / 5;
    for (int s = 0; s < 5; ++s)
        zero_slice_kernel<<<(per + 255) / 256, 256>>>(s);

    dim3 grid(IMW / TILE_W, IMH / TILE_H, NCH);
    dim3 block(32, TILE_H);
    predict_kernel<<<grid, block>>>(x, prm);
    finalize_kernel<<<1, 256>>>((float*)d_out);
}

// round 8
// speedup vs baseline: 3.9786x; 3.9786x over previous
#include <cuda_runtime.h>
#include <cuda_fp16.h>
#include <math.h>
#include <cstdint>

#define IMW 512
#define IMH 512
#define NCH 12
#define NBINS 256
#define NT 256          // 8 warps; warp w handles row gy0+w, 32 px wide

struct Params { const float* p[27]; };

__device__ double g_sumsq[2];                    // [0]=x, [1]=delta
__device__ unsigned int g_hist[2][NCH][NBINS];   // [0]=x, [1]=delta

#define ZTOTAL (2 * NCH * NBINS)
__global__ void zero_slice_kernel(int slice) {
    const int per = (ZTOTAL + 4) / 5;
    int i = slice * per + blockIdx.x * blockDim.x + threadIdx.x;
    if (i < (slice + 1) * per && i < ZTOTAL) ((unsigned int*)g_hist)[i] = 0u;
    if (slice == 0 && blockIdx.x == 0 && threadIdx.x < 2) g_sumsq[threadIdx.x] = 0.0;
}

__device__ __forceinline__ float leaky(float v) { return fmaxf(v, 0.01f * v); }

__device__ __forceinline__ uint32_t packh2(float lo, float hi) {
    __half2 h = __floats2half2_rn(lo, hi);
    return *reinterpret_cast<uint32_t*>(&h);
}

// m16n8k16 fp16 MMA, fp32 accumulate (in-place D += A*B)
__device__ __forceinline__ void mma16816(float* d, const uint32_t* a, const uint32_t* b) {
    asm volatile(
        "mma.sync.aligned.m16n8k16.row.col.f32.f16.f16.f32 "
        "{%0,%1,%2,%3}, {%4,%5,%6,%7}, {%8,%9}, {%0,%1,%2,%3};"
        : "+f"(d[0]), "+f"(d[1]), "+f"(d[2]), "+f"(d[3])
        : "r"(a[0]), "r"(a[1]), "r"(a[2]), "r"(a[3]), "r"(b[0]), "r"(b[1]));
}

// B-fragment tiles per predictor: layer l (0..2): tiles l*8 + kt*4 + nt ; head: 24 + kt
#define TILES_PER_PRED 26

__global__ __launch_bounds__(NT) void predict_kernel(const float* __restrict__ x, Params prm) {
    __shared__ uint2 s_bf[3][TILES_PER_PRED][32];   // B fragments, one LDS.64 per (tile,lane)
    __shared__ float s_tile[11][40];                // 8 rows + 3 halo, 32 cols + 6 halo (38 used)
    __shared__ float2 s_bias2[3][3][4][4];          // [pred][layer][ntile][tig] = (b[n0], b[n0+1])
    __shared__ float s_b3[3];
    __shared__ unsigned int s_hist[2][NBINS];
    __shared__ double s_red[2][NT / 32];

    const int lane = threadIdx.x;
    const int wr   = threadIdx.y;       // warp row (0..7)
    const int tid  = wr * 32 + lane;
    const int tig  = lane & 3;          // thread-in-group
    const int g    = lane >> 2;         // group id (row base)
    const int ch   = blockIdx.z;
    const int gx0  = blockIdx.x * 32;
    const int gy0  = blockIdx.y * 8;

    for (int i = tid; i < 2 * NBINS; i += NT) ((unsigned int*)s_hist)[i] = 0u;

    // ---- stage B fragments (weights -> fp16 mma layout) ----
    for (int i = tid; i < 3 * TILES_PER_PRED * 32; i += NT) {
        int p = i / (TILES_PER_PRED * 32);
        int rem = i % (TILES_PER_PRED * 32);
        int tile = rem / 32, ln = rem % 32;
        int ltig = ln & 3, lg = ln >> 2;
        float w[4];
        if (tile < 24) {
            int l = tile / 8, r8 = tile % 8, kt = r8 / 4, nt = r8 % 4;
            int n = nt * 8 + lg;
            int kb = kt * 16 + 2 * ltig;
            int ks[4] = {kb, kb + 1, kb + 8, kb + 9};
            if (l == 0) {
                const float* wT = prm.p[p * 9 + 0];
                const float* wL = prm.p[p * 9 + 2];
#pragma unroll
                for (int j = 0; j < 4; ++j) {
                    int k = ks[j];
                    w[j] = (k < 21) ? wT[n * 21 + k] : (k < 24 ? wL[n * 3 + (k - 21)] : 0.f);
                }
            } else {
                const float* wm = prm.p[p * 9 + (l == 1 ? 3 : 5)];
#pragma unroll
                for (int j = 0; j < 4; ++j) w[j] = wm[n * 32 + ks[j]];
            }
        } else {
            int kt = tile - 24;
            const float* w3 = prm.p[p * 9 + 7];
            int kb = kt * 16 + 2 * ltig;
#pragma unroll
            for (int j = 0; j < 4; ++j) {
                int k = kb + (j & 1) + (j >> 1) * 8;
                w[j] = (lg == 0) ? w3[k] : 0.f;
            }
        }
        uint2 v;
        v.x = packh2(w[0], w[1]);
        v.y = packh2(w[2], w[3]);
        s_bf[p][tile][ln] = v;
    }

    // biases
    for (int i = tid; i < 3 * 3 * 16; i += NT) {
        int p = i / 48, r = i % 48, l = r / 16, q = r % 16;  // q = nt*4 + tig
        int nt = q / 4, tg = q % 4;
        const float* b = prm.p[p * 9 + (l == 0 ? 1 : (l == 1 ? 4 : 6))];
        int n0 = nt * 8 + 2 * tg;
        s_bias2[p][l][nt][tg] = make_float2(b[n0], b[n0 + 1]);
    }
    if (tid < 3) s_b3[tid] = prm.p[tid * 9 + 8][0];

    // ---- stage input tile with halo (top 3 rows, left/right 3 cols) ----
    const float* xch = x + (size_t)ch * IMH * IMW;
    for (int i = tid; i < 11 * 38; i += NT) {
        int r = i / 38, c = i % 38;
        int gr = gy0 - 3 + r, gc = gx0 - 3 + c;
        float v = 0.f;
        if (gr >= 0 && gc >= 0 && gc < IMW) v = xch[gr * IMW + gc];
        s_tile[r][c] = v;
    }
    __syncthreads();

    float ph[3][2][2];   // [pred][mtile][rowhalf], valid at tig==0
    double acc_x = 0.0, acc_d = 0.0;

#pragma unroll 1
    for (int m = 0; m < 2; ++m) {
        const int px0 = m * 16 + g;        // row g
        const int px1 = px0 + 8;           // row g+8

        // ---- build layer-0 A fragments from taps ----
        // tap(px, k): k<21 -> s_tile[wr + k/7][px + k%7]; else s_tile[wr+3][px + k-21]
        uint32_t A0[2][4];
#pragma unroll
        for (int kt = 0; kt < 2; ++kt) {
            const int kb = kt * 16 + 2 * tig;
#define TAP(px, k) ((k) < 21 ? s_tile[wr + (k) / 7][(px) + (k) % 7] : s_tile[wr + 3][(px) + (k) - 21])
            A0[kt][0] = packh2(TAP(px0, kb), TAP(px0, kb + 1));
            A0[kt][1] = packh2(TAP(px1, kb), TAP(px1, kb + 1));
            if (kt == 0) {
                A0[kt][2] = packh2(TAP(px0, kb + 8), TAP(px0, kb + 9));
                A0[kt][3] = packh2(TAP(px1, kb + 8), TAP(px1, kb + 9));
            } else {
                A0[kt][2] = 0u;   // k >= 24 taps are zero
                A0[kt][3] = 0u;
            }
#undef TAP
        }

#pragma unroll 1
        for (int p = 0; p < 3; ++p) {
            uint32_t A[2][4];
#pragma unroll
            for (int kt = 0; kt < 2; ++kt)
#pragma unroll
                for (int j = 0; j < 4; ++j) A[kt][j] = A0[kt][j];

            // ---- layers 0,1,2 ----
#pragma unroll
            for (int l = 0; l < 3; ++l) {
                float D[4][4];
#pragma unroll
                for (int nt = 0; nt < 4; ++nt)
#pragma unroll
                    for (int j = 0; j < 4; ++j) D[nt][j] = 0.f;

#pragma unroll
                for (int kt = 0; kt < 2; ++kt) {
#pragma unroll
                    for (int nt = 0; nt < 4; ++nt) {
                        uint2 bv = s_bf[p][l * 8 + kt * 4 + nt][lane];
                        uint32_t br[2] = {bv.x, bv.y};
                        mma16816(D[nt], A[kt], br);
                    }
                }
                // epilogue: bias + leaky + repack into next A (lane-local!)
#pragma unroll
                for (int nt = 0; nt < 4; ++nt) {
                    float2 b2 = s_bias2[p][l][nt][tig];
                    float v0 = leaky(D[nt][0] + b2.x);
                    float v1 = leaky(D[nt][1] + b2.y);
                    float v2 = leaky(D[nt][2] + b2.x);
                    float v3 = leaky(D[nt][3] + b2.y);
                    A[nt / 2][(nt % 2) * 2 + 0] = packh2(v0, v1);
                    A[nt / 2][(nt % 2) * 2 + 1] = packh2(v2, v3);
                }
            }

            // ---- head: 32 -> 1 via mma (only n=0 column non-zero) ----
            float Dh[4] = {0.f, 0.f, 0.f, 0.f};
            {
                uint2 b0 = s_bf[p][24][lane];
                uint2 b1 = s_bf[p][25][lane];
                uint32_t br0[2] = {b0.x, b0.y};
                uint32_t br1[2] = {b1.x, b1.y};
                mma16816(Dh, A[0], br0);
                mma16816(Dh, A[1], br1);
            }
            if (tig == 0) {
                float b3 = s_b3[p];
                ph[p][m][0] = fminf(fmaxf(Dh[0] + b3, -1.f), 1.f);   // row g
                ph[p][m][1] = fminf(fmaxf(Dh[2] + b3, -1.f), 1.f);   // row g+8
            }
        }
    }

    // ---- stats: tig==0 lanes own 4 pixels each ----
    if (tig == 0) {
#pragma unroll
        for (int m = 0; m < 2; ++m) {
#pragma unroll
            for (int hh = 0; hh < 2; ++hh) {
                int px = m * 16 + g + hh * 8;
                float x0 = s_tile[wr + 3][px + 3];
                float pa = ph[0][m][hh], pb = ph[1][m][hh], pc = ph[2][m][hh];
                float med = fmaxf(fminf(pa, fmaxf(pb, pc)), fminf(pb, pc));
                float delta = fmodf(x0 - med + 1.0f, 2.0f) - 1.0f;

                if (x0 >= -1.f && x0 <= 1.f) {
                    int idx = (int)floorf((x0 + 1.f) * 128.f);
                    idx = min(max(idx, 0), NBINS - 1);
                    atomicAdd(&s_hist[0][idx], 1u);
                }
                if (delta >= -1.f && delta <= 1.f) {
                    int idx = (int)floorf((delta + 1.f) * 128.f);
                    idx = min(max(idx, 0), NBINS - 1);
                    atomicAdd(&s_hist[1][idx], 1u);
                }
                acc_x += (double)x0 * (double)x0;
                acc_d += (double)delta * (double)delta;
            }
        }
    }

    // ---- reductions ----
#pragma unroll
    for (int o = 16; o > 0; o >>= 1) {
        acc_x += __shfl_down_sync(0xffffffffu, acc_x, o);
        acc_d += __shfl_down_sync(0xffffffffu, acc_d, o);
    }
    if (lane == 0) { s_red[0][wr] = acc_x; s_red[1][wr] = acc_d; }
    __syncthreads();
    if (tid == 0) {
        double sx = 0.0, sd = 0.0;
#pragma unroll
        for (int i = 0; i < NT / 32; ++i) { sx += s_red[0][i]; sd += s_red[1][i]; }
        atomicAdd(&g_sumsq[0], sx);
        atomicAdd(&g_sumsq[1], sd);
    }
    if (tid < NBINS) {
        unsigned c0 = s_hist[0][tid], c1 = s_hist[1][tid];
        if (c0) atomicAdd(&g_hist[0][ch][tid], c0);
        if (c1) atomicAdd(&g_hist[1][ch][tid], c1);
    }
}

__global__ void finalize_kernel(float* out) {
    __shared__ double s_ent[2][8];
    const int tid = threadIdx.x;
    double e0 = 0.0, e1 = 0.0;
    const double res = (double)(IMH * IMW);
    for (int i = tid; i < NCH * NBINS; i += 256) {
        unsigned c0 = ((const unsigned*)g_hist[0])[i];
        unsigned c1 = ((const unsigned*)g_hist[1])[i];
        if (c0) { double pp = (double)c0 / res; e0 -= pp * log2(pp); }
        if (c1) { double pp = (double)c1 / res; e1 -= pp * log2(pp); }
    }
#pragma unroll
    for (int o = 16; o > 0; o >>= 1) {
        e0 += __shfl_down_sync(0xffffffffu, e0, o);
        e1 += __shfl_down_sync(0xffffffffu, e1, o);
    }
    if ((tid & 31) == 0) { s_ent[0][tid >> 5] = e0; s_ent[1][tid >> 5] = e1; }
    __syncthreads();
    if (tid == 0) {
        double E0 = 0.0, E1 = 0.0;
#pragma unroll
        for (int i = 0; i < 8; ++i) { E0 += s_ent[0][i]; E1 += s_ent[1][i]; }
        const double N = (double)NCH * IMH * IMW;
        out[0] = (float)(255.0 * sqrt(g_sumsq[1] / N));   // loss1
        out[1] = (float)(255.0 * sqrt(g_sumsq[0] / N));   // loss0
        out[2] = (float)(E0 / (8.0 * NCH));               // invCR0
        out[3] = (float)(E1 / (8.0 * NCH));               // invCR1
    }
}

extern "C" void kernel_launch(void* const* d_in, const int* in_sizes, int n_in,
                              void* d_out, int out_size) {
    const float* x = (const float*)d_in[0];
    Params prm;
    for (int i = 0; i < 27; ++i) prm.p[i] = (const float*)d_in[1 + i];

    const int per = (ZTOTAL + 4) / 5;
    for (int s = 0; s < 5; ++s)
        zero_slice_kernel<<<(per + 255) / 256, 256>>>(s);

    dim3 grid(IMW / 32, IMH / 8, NCH);
    dim3 block(32, 8);
    predict_kernel<<<grid, block>>>(x, prm);
    finalize_kernel<<<1, 256>>>((float*)d_out);
}